// round 1
// baseline (speedup 1.0000x reference)
#include <cuda_runtime.h>
#include <cstdint>
#include <cstddef>

// Problem constants
#define LP   197
#define BT   128
#define DIM  768
#define CA   192
#define TT   8

// SMEM strides (floats), chosen for conflict-free fragment access
#define GP   196   // Gs:  128 x 196   (h / gelu(g) tile; 196 % 32 == 4)
#define AP   36    // As:  128 x 36    (x chunk 128x32;   36 % 32 == 4)
#define B1P  200   // Bs1: 32  x 200   (w1 chunk 32x192; 200 % 32 == 8)
#define W2P  136   // Ws2: 192 x 136   (w2 chunk 192x128;136 % 32 == 8)

#define SMEM_FLOATS (128*GP + 128*AP + 192*W2P)
#define SMEM_BYTES  (SMEM_FLOATS * 4)   // 223232 B

__device__ __forceinline__ float tf32r(float v) {
    uint32_t u;
    asm("cvt.rna.tf32.f32 %0, %1;" : "=r"(u) : "f"(v));
    return __uint_as_float(u);
}

__device__ __forceinline__ void mma_tf32(float c[4], const uint32_t a[4], const uint32_t b[2]) {
    asm volatile(
        "mma.sync.aligned.m16n8k8.row.col.f32.tf32.tf32.f32 "
        "{%0,%1,%2,%3}, {%4,%5,%6,%7}, {%8,%9}, {%0,%1,%2,%3};\n"
        : "+f"(c[0]), "+f"(c[1]), "+f"(c[2]), "+f"(c[3])
        : "r"(a[0]), "r"(a[1]), "r"(a[2]), "r"(a[3]),
          "r"(b[0]), "r"(b[1]));
}

__device__ __forceinline__ float gelu_exact(float v) {
    return 0.5f * v * (1.0f + erff(v * 0.70710678118654752f));
}

__global__ void __launch_bounds__(256, 1)
fused_adapter_kernel(const float* __restrict__ x,
                     const float* __restrict__ w1,
                     const float* __restrict__ b1,
                     const float* __restrict__ cw,   // (CA,3)
                     const float* __restrict__ cb,   // (CA,)
                     const float* __restrict__ w2,
                     const float* __restrict__ b2,
                     float* __restrict__ out)
{
    extern __shared__ float smem[];
    float* Gs = smem;                 // 128 x GP : h tile -> g tile -> gelu(g) (tf32)
    float* As = smem + 128 * GP;      // 128 x AP : GEMM1 A staging
    float* Bs = As + 128 * AP;        // union: GEMM1 B chunk / GEMM2 B chunk

    const int tid  = threadIdx.x;
    const int wid  = tid >> 5;
    const int lane = tid & 31;
    const int gid  = lane >> 2;   // group id (0..7)
    const int ctig = lane & 3;    // thread in group (0..3)

    const int l    = blockIdx.x;
    const int lsrc = (l == 0) ? 1 : l;   // position 0 output = gelu(h at pos 1), no mixing

    const int wm = wid & 3;   // warp m index: rows wm*32 .. +31
    const int wn = wid >> 2;  // warp n index (GEMM1: cols wn*96 .. ; GEMM2: wn*64 ..)

    // ================= GEMM1: h(128x192) = x[lsrc](128x768) @ w1 + b1 =================
    float acc[2][12][4];
    #pragma unroll
    for (int i = 0; i < 2; i++)
        #pragma unroll
        for (int j = 0; j < 12; j++)
            #pragma unroll
            for (int k = 0; k < 4; k++) acc[i][j][k] = 0.0f;

    const float* xA = x + (size_t)lsrc * BT * DIM;

    #pragma unroll 1
    for (int kc = 0; kc < DIM; kc += 32) {
        // stage A: 128 x 32 of x, tf32-rounded
        #pragma unroll
        for (int i = 0; i < 4; i++) {
            int idx = tid + (i << 8);
            int row = idx >> 3;
            int c4  = (idx & 7) << 2;
            float4 v = *(const float4*)(xA + (size_t)row * DIM + kc + c4);
            v.x = tf32r(v.x); v.y = tf32r(v.y); v.z = tf32r(v.z); v.w = tf32r(v.w);
            *(float4*)(As + row * AP + c4) = v;
        }
        // stage B: 32 x 192 of w1, tf32-rounded
        #pragma unroll
        for (int i = 0; i < 6; i++) {
            int idx = tid + (i << 8);
            int row = idx / 48;
            int c4  = (idx % 48) << 2;
            float4 v = *(const float4*)(w1 + (size_t)(kc + row) * CA + c4);
            v.x = tf32r(v.x); v.y = tf32r(v.y); v.z = tf32r(v.z); v.w = tf32r(v.w);
            *(float4*)(Bs + row * B1P + c4) = v;
        }
        __syncthreads();

        #pragma unroll
        for (int ks = 0; ks < 4; ks++) {
            int k0 = ks << 3;
            uint32_t a[2][4];
            #pragma unroll
            for (int mt = 0; mt < 2; mt++) {
                int r0 = wm * 32 + mt * 16 + gid;
                a[mt][0] = __float_as_uint(As[r0 * AP + k0 + ctig]);
                a[mt][1] = __float_as_uint(As[(r0 + 8) * AP + k0 + ctig]);
                a[mt][2] = __float_as_uint(As[r0 * AP + k0 + ctig + 4]);
                a[mt][3] = __float_as_uint(As[(r0 + 8) * AP + k0 + ctig + 4]);
            }
            #pragma unroll
            for (int nt = 0; nt < 12; nt++) {
                uint32_t b[2];
                int n0 = wn * 96 + nt * 8 + gid;
                b[0] = __float_as_uint(Bs[(k0 + ctig) * B1P + n0]);
                b[1] = __float_as_uint(Bs[(k0 + ctig + 4) * B1P + n0]);
                mma_tf32(acc[0][nt], a[0], b);
                mma_tf32(acc[1][nt], a[1], b);
            }
        }
        __syncthreads();
    }

    // store h + b1 into Gs
    #pragma unroll
    for (int mt = 0; mt < 2; mt++) {
        #pragma unroll
        for (int nt = 0; nt < 12; nt++) {
            int r0 = wm * 32 + mt * 16 + gid;
            int c0 = wn * 96 + nt * 8 + 2 * ctig;
            float bb0 = b1[c0], bb1 = b1[c0 + 1];
            Gs[r0 * GP + c0]           = acc[mt][nt][0] + bb0;
            Gs[r0 * GP + c0 + 1]       = acc[mt][nt][1] + bb1;
            Gs[(r0 + 8) * GP + c0]     = acc[mt][nt][2] + bb0;
            Gs[(r0 + 8) * GP + c0 + 1] = acc[mt][nt][3] + bb1;
        }
    }
    __syncthreads();

    // ================= Temporal mixing (only for l >= 1) =================
    // g[b*8+t, c] = h[b*8+t, c] + (sum_t alpha_t(c) * h[b*8+t, c]) / 28 + cb[c]
    if (l > 0) {
        #pragma unroll 1
        for (int i = 0; i < 12; i++) {
            int task = tid + (i << 8);          // 16 b-groups * 192 channels
            int b = task / CA;
            int c = task % CA;
            float cw0 = cw[c * 3 + 0];
            float cw1 = cw[c * 3 + 1];
            float cw2 = cw[c * 3 + 2];
            float cbc = cb[c];
            float hv[TT];
            float S = 0.0f;
            #pragma unroll
            for (int t = 0; t < TT; t++) {
                hv[t] = Gs[(b * TT + t) * GP + c];
                float w = cw1 * (float)t - (float)(TT - 1 - t);
                if (t < TT - 1) w += cw0 * (float)(t + 1);
                if (t >= 1)     w += cw2 * (float)(t - 1);
                S += w * hv[t];
            }
            float r = S * (1.0f / 28.0f) + cbc;
            #pragma unroll
            for (int t = 0; t < TT; t++)
                Gs[(b * TT + t) * GP + c] = hv[t] + r;
        }
        __syncthreads();
    }

    // ================= GELU (exact) + tf32 round, in place =================
    #pragma unroll 4
    for (int i = 0; i < 96; i++) {
        int idx = tid + (i << 8);          // 128*192 elements
        int r = idx / CA;
        int c = idx % CA;
        float v = Gs[r * GP + c];
        Gs[r * GP + c] = tf32r(gelu_exact(v));
    }
    __syncthreads();

    // ================= GEMM2: out[l] = gelu(g)(128x192) @ w2 + b2 + x[l] =================
    const float* xR   = x   + (size_t)l * BT * DIM;
    float*       outR = out + (size_t)l * BT * DIM;

    #pragma unroll 1
    for (int nc = 0; nc < 6; nc++) {
        int nbase = nc * 128;
        // stage w2 chunk: 192 x 128, tf32-rounded
        #pragma unroll
        for (int i = 0; i < 24; i++) {
            int idx = tid + (i << 8);
            int row = idx >> 5;
            int c4  = (idx & 31) << 2;
            float4 v = *(const float4*)(w2 + (size_t)row * DIM + nbase + c4);
            v.x = tf32r(v.x); v.y = tf32r(v.y); v.z = tf32r(v.z); v.w = tf32r(v.w);
            *(float4*)(Bs + row * W2P + c4) = v;
        }
        __syncthreads();

        float acc2[2][8][4];
        #pragma unroll
        for (int i = 0; i < 2; i++)
            #pragma unroll
            for (int j = 0; j < 8; j++)
                #pragma unroll
                for (int k = 0; k < 4; k++) acc2[i][j][k] = 0.0f;

        #pragma unroll
        for (int ks = 0; ks < 24; ks++) {
            int k0 = ks << 3;
            uint32_t a[2][4];
            #pragma unroll
            for (int mt = 0; mt < 2; mt++) {
                int r0 = wm * 32 + mt * 16 + gid;
                a[mt][0] = __float_as_uint(Gs[r0 * GP + k0 + ctig]);
                a[mt][1] = __float_as_uint(Gs[(r0 + 8) * GP + k0 + ctig]);
                a[mt][2] = __float_as_uint(Gs[r0 * GP + k0 + ctig + 4]);
                a[mt][3] = __float_as_uint(Gs[(r0 + 8) * GP + k0 + ctig + 4]);
            }
            #pragma unroll
            for (int nt = 0; nt < 8; nt++) {
                uint32_t b[2];
                int n0 = wn * 64 + nt * 8 + gid;
                b[0] = __float_as_uint(Bs[(k0 + ctig) * W2P + n0]);
                b[1] = __float_as_uint(Bs[(k0 + ctig + 4) * W2P + n0]);
                mma_tf32(acc2[0][nt], a[0], b);
                mma_tf32(acc2[1][nt], a[1], b);
            }
        }
        __syncthreads();

        // epilogue: + b2 + x residual, store
        #pragma unroll
        for (int mt = 0; mt < 2; mt++) {
            #pragma unroll
            for (int nt = 0; nt < 8; nt++) {
                int r0  = wm * 32 + mt * 16 + gid;
                int c0g = nbase + wn * 64 + nt * 8 + 2 * ctig;
                float bb0 = b2[c0g], bb1 = b2[c0g + 1];
                size_t o0 = (size_t)r0 * DIM + c0g;
                float2 xr0 = *(const float2*)(xR + o0);
                float2 ov0;
                ov0.x = xr0.x + acc2[mt][nt][0] + bb0;
                ov0.y = xr0.y + acc2[mt][nt][1] + bb1;
                *(float2*)(outR + o0) = ov0;
                size_t o1 = o0 + (size_t)8 * DIM;
                float2 xr1 = *(const float2*)(xR + o1);
                float2 ov1;
                ov1.x = xr1.x + acc2[mt][nt][2] + bb0;
                ov1.y = xr1.y + acc2[mt][nt][3] + bb1;
                *(float2*)(outR + o1) = ov1;
            }
        }
    }
}

extern "C" void kernel_launch(void* const* d_in, const int* in_sizes, int n_in,
                              void* d_out, int out_size) {
    const float* x  = (const float*)d_in[0];
    const float* w1 = (const float*)d_in[1];
    const float* b1 = (const float*)d_in[2];
    const float* cw = (const float*)d_in[3];
    const float* cb = (const float*)d_in[4];
    const float* w2 = (const float*)d_in[5];
    const float* b2 = (const float*)d_in[6];
    float* out = (float*)d_out;

    cudaFuncSetAttribute(fused_adapter_kernel,
                         cudaFuncAttributeMaxDynamicSharedMemorySize, SMEM_BYTES);
    fused_adapter_kernel<<<LP, 256, SMEM_BYTES>>>(x, w1, b1, cw, cb, w2, b2, out);
}

// round 2
// speedup vs baseline: 1.0797x; 1.0797x over previous
#include <cuda_runtime.h>
#include <cstdint>
#include <cstddef>

// Problem constants
#define LP   197
#define BT   128
#define DIM  768
#define CA   192
#define TT   8
#define ROWS 64          // rows per CTA (two CTAs per position l)

// SMEM strides (floats), chosen for conflict-free fragment access
#define GP   196   // Gs:  64 x 196   (h / gelu(g) tile)      -> banks 4*gid+ctig
#define AP   36    // As:  64 x 36    (x chunk 64x32)
#define B1P  200   // Bs1: 32 x 200   (w1 chunk 32x192)       -> banks 8*ctig+gid
#define W2P  72    // Ws2: 192 x 72   (w2 chunk 192x64)       -> banks 8*ctig+gid

#define GS_F   (ROWS * GP)          // 12544
#define AS_F   (ROWS * AP)          // 2304
#define BS_F   (192 * W2P)          // 13824 (>= 32*B1P = 6400)
#define SMEM_FLOATS (GS_F + AS_F + BS_F)
#define SMEM_BYTES  (SMEM_FLOATS * 4)   // 114688 B -> 2 CTAs/SM

__device__ __forceinline__ float tf32r(float v) {
    uint32_t u;
    asm("cvt.rna.tf32.f32 %0, %1;" : "=r"(u) : "f"(v));
    return __uint_as_float(u);
}

__device__ __forceinline__ void mma_tf32(float c[4], const uint32_t a[4], const uint32_t b[2]) {
    asm volatile(
        "mma.sync.aligned.m16n8k8.row.col.f32.tf32.tf32.f32 "
        "{%0,%1,%2,%3}, {%4,%5,%6,%7}, {%8,%9}, {%0,%1,%2,%3};\n"
        : "+f"(c[0]), "+f"(c[1]), "+f"(c[2]), "+f"(c[3])
        : "r"(a[0]), "r"(a[1]), "r"(a[2]), "r"(a[3]),
          "r"(b[0]), "r"(b[1]));
}

__device__ __forceinline__ float gelu_exact(float v) {
    return 0.5f * v * (1.0f + erff(v * 0.70710678118654752f));
}

__global__ void __launch_bounds__(256, 2)
fused_adapter_kernel(const float* __restrict__ x,
                     const float* __restrict__ w1,
                     const float* __restrict__ b1,
                     const float* __restrict__ cw,   // (CA,3)
                     const float* __restrict__ cb,   // (CA,)
                     const float* __restrict__ w2,
                     const float* __restrict__ b2,
                     float* __restrict__ out)
{
    extern __shared__ float smem[];
    float* Gs = smem;                 // 64 x GP
    float* As = smem + GS_F;          // 64 x AP
    float* Bs = As + AS_F;            // union: GEMM1 B chunk / GEMM2 W2 chunk

    const int tid  = threadIdx.x;
    const int wid  = tid >> 5;
    const int lane = tid & 31;
    const int gid  = lane >> 2;   // 0..7
    const int ctig = lane & 3;    // 0..3

    const int l    = blockIdx.x >> 1;
    const int half = blockIdx.x & 1;
    const int lsrc = (l == 0) ? 1 : l;   // position 0: gelu(h at pos 1), no mixing

    // GEMM1 warp layout: wm in {0,1} (32 rows), wn1 in {0..3} (48 cols, nt=6)
    const int wm  = wid & 1;
    const int wn1 = wid >> 1;

    // ================= GEMM1: h(64x192) = x_slice(64x768) @ w1 + b1 =================
    float acc[2][6][4];
    #pragma unroll
    for (int i = 0; i < 2; i++)
        #pragma unroll
        for (int j = 0; j < 6; j++)
            #pragma unroll
            for (int k = 0; k < 4; k++) acc[i][j][k] = 0.0f;

    const float* xA = x + ((size_t)lsrc * BT + half * ROWS) * DIM;

    #pragma unroll 1
    for (int kc = 0; kc < DIM; kc += 32) {
        // stage A: 64 x 32 of x, tf32-rounded (512 float4)
        #pragma unroll
        for (int i = 0; i < 2; i++) {
            int idx = tid + (i << 8);
            int row = idx >> 3;
            int c4  = (idx & 7) << 2;
            float4 v = *(const float4*)(xA + (size_t)row * DIM + kc + c4);
            v.x = tf32r(v.x); v.y = tf32r(v.y); v.z = tf32r(v.z); v.w = tf32r(v.w);
            *(float4*)(As + row * AP + c4) = v;
        }
        // stage B: 32 x 192 of w1, tf32-rounded (1536 float4)
        #pragma unroll
        for (int i = 0; i < 6; i++) {
            int idx = tid + (i << 8);
            int row = idx / 48;
            int c4  = (idx % 48) << 2;
            float4 v = *(const float4*)(w1 + (size_t)(kc + row) * CA + c4);
            v.x = tf32r(v.x); v.y = tf32r(v.y); v.z = tf32r(v.z); v.w = tf32r(v.w);
            *(float4*)(Bs + row * B1P + c4) = v;
        }
        __syncthreads();

        #pragma unroll
        for (int ks = 0; ks < 4; ks++) {
            int k0 = ks << 3;
            uint32_t a[2][4];
            #pragma unroll
            for (int mt = 0; mt < 2; mt++) {
                int r0 = wm * 32 + mt * 16 + gid;
                a[mt][0] = __float_as_uint(As[r0 * AP + k0 + ctig]);
                a[mt][1] = __float_as_uint(As[(r0 + 8) * AP + k0 + ctig]);
                a[mt][2] = __float_as_uint(As[r0 * AP + k0 + ctig + 4]);
                a[mt][3] = __float_as_uint(As[(r0 + 8) * AP + k0 + ctig + 4]);
            }
            #pragma unroll
            for (int nt = 0; nt < 6; nt++) {
                uint32_t b[2];
                int n0 = wn1 * 48 + nt * 8 + gid;
                b[0] = __float_as_uint(Bs[(k0 + ctig) * B1P + n0]);
                b[1] = __float_as_uint(Bs[(k0 + ctig + 4) * B1P + n0]);
                mma_tf32(acc[0][nt], a[0], b);
                mma_tf32(acc[1][nt], a[1], b);
            }
        }
        __syncthreads();
    }

    // store h + b1 into Gs
    #pragma unroll
    for (int mt = 0; mt < 2; mt++) {
        #pragma unroll
        for (int nt = 0; nt < 6; nt++) {
            int r0 = wm * 32 + mt * 16 + gid;
            int c0 = wn1 * 48 + nt * 8 + 2 * ctig;
            float bb0 = b1[c0], bb1 = b1[c0 + 1];
            Gs[r0 * GP + c0]           = acc[mt][nt][0] + bb0;
            Gs[r0 * GP + c0 + 1]       = acc[mt][nt][1] + bb1;
            Gs[(r0 + 8) * GP + c0]     = acc[mt][nt][2] + bb0;
            Gs[(r0 + 8) * GP + c0 + 1] = acc[mt][nt][3] + bb1;
        }
    }
    __syncthreads();

    // ================= Temporal mixing (only for l >= 1) =================
    if (l > 0) {
        #pragma unroll 1
        for (int i = 0; i < 6; i++) {
            int task = tid + (i << 8);          // 8 b-groups * 192 channels
            int b = task / CA;
            int c = task % CA;
            float cw0 = cw[c * 3 + 0];
            float cw1 = cw[c * 3 + 1];
            float cw2 = cw[c * 3 + 2];
            float cbc = cb[c];
            float hv[TT];
            float S = 0.0f;
            #pragma unroll
            for (int t = 0; t < TT; t++) {
                hv[t] = Gs[(b * TT + t) * GP + c];
                float w = cw1 * (float)t - (float)(TT - 1 - t);
                if (t < TT - 1) w += cw0 * (float)(t + 1);
                if (t >= 1)     w += cw2 * (float)(t - 1);
                S += w * hv[t];
            }
            float r = S * (1.0f / 28.0f) + cbc;
            #pragma unroll
            for (int t = 0; t < TT; t++)
                Gs[(b * TT + t) * GP + c] = hv[t] + r;
        }
        __syncthreads();
    }

    // ================= GELU (exact) + tf32 round, in place =================
    #pragma unroll 4
    for (int i = 0; i < 48; i++) {
        int idx = tid + (i << 8);          // 64*192 elements
        int r = idx / CA;
        int c = idx % CA;
        float v = Gs[r * GP + c];
        Gs[r * GP + c] = tf32r(gelu_exact(v));
    }
    __syncthreads();

    // ================= GEMM2: out = gelu(g)(64x192) @ w2 + b2 + x =================
    const float* xR   = x   + ((size_t)l * BT + half * ROWS) * DIM;
    float*       outR = out + ((size_t)l * BT + half * ROWS) * DIM;

    // GEMM2 warp layout: wm (32 rows, mt=2), wn2 in {0..3} (16 cols, nt=2)
    #pragma unroll 1
    for (int nc = 0; nc < 12; nc++) {
        int nbase = nc * 64;
        // stage w2 chunk: 192 x 64, tf32-rounded (3072 float4)
        #pragma unroll
        for (int i = 0; i < 12; i++) {
            int idx = tid + (i << 8);
            int row = idx >> 4;
            int c4  = (idx & 15) << 2;
            float4 v = *(const float4*)(w2 + (size_t)row * DIM + nbase + c4);
            v.x = tf32r(v.x); v.y = tf32r(v.y); v.z = tf32r(v.z); v.w = tf32r(v.w);
            *(float4*)(Bs + row * W2P + c4) = v;
        }
        __syncthreads();

        float acc2[2][2][4];
        #pragma unroll
        for (int i = 0; i < 2; i++)
            #pragma unroll
            for (int j = 0; j < 2; j++)
                #pragma unroll
                for (int k = 0; k < 4; k++) acc2[i][j][k] = 0.0f;

        #pragma unroll
        for (int ks = 0; ks < 24; ks++) {
            int k0 = ks << 3;
            uint32_t a[2][4];
            #pragma unroll
            for (int mt = 0; mt < 2; mt++) {
                int r0 = wm * 32 + mt * 16 + gid;
                a[mt][0] = __float_as_uint(Gs[r0 * GP + k0 + ctig]);
                a[mt][1] = __float_as_uint(Gs[(r0 + 8) * GP + k0 + ctig]);
                a[mt][2] = __float_as_uint(Gs[r0 * GP + k0 + ctig + 4]);
                a[mt][3] = __float_as_uint(Gs[(r0 + 8) * GP + k0 + ctig + 4]);
            }
            #pragma unroll
            for (int nt = 0; nt < 2; nt++) {
                uint32_t b[2];
                int n0 = (wid >> 1) * 16 + nt * 8 + gid;
                b[0] = __float_as_uint(Bs[(k0 + ctig) * W2P + n0]);
                b[1] = __float_as_uint(Bs[(k0 + ctig + 4) * W2P + n0]);
                mma_tf32(acc2[0][nt], a[0], b);
                mma_tf32(acc2[1][nt], a[1], b);
            }
        }
        __syncthreads();

        // epilogue: + b2 + x residual, store
        #pragma unroll
        for (int mt = 0; mt < 2; mt++) {
            #pragma unroll
            for (int nt = 0; nt < 2; nt++) {
                int r0  = wm * 32 + mt * 16 + gid;
                int c0g = nbase + (wid >> 1) * 16 + nt * 8 + 2 * ctig;
                float bb0 = b2[c0g], bb1 = b2[c0g + 1];
                size_t o0 = (size_t)r0 * DIM + c0g;
                float2 xr0 = *(const float2*)(xR + o0);
                float2 ov0;
                ov0.x = xr0.x + acc2[mt][nt][0] + bb0;
                ov0.y = xr0.y + acc2[mt][nt][1] + bb1;
                *(float2*)(outR + o0) = ov0;
                size_t o1 = o0 + (size_t)8 * DIM;
                float2 xr1 = *(const float2*)(xR + o1);
                float2 ov1;
                ov1.x = xr1.x + acc2[mt][nt][2] + bb0;
                ov1.y = xr1.y + acc2[mt][nt][3] + bb1;
                *(float2*)(outR + o1) = ov1;
            }
        }
    }
}

extern "C" void kernel_launch(void* const* d_in, const int* in_sizes, int n_in,
                              void* d_out, int out_size) {
    const float* x  = (const float*)d_in[0];
    const float* w1 = (const float*)d_in[1];
    const float* b1 = (const float*)d_in[2];
    const float* cw = (const float*)d_in[3];
    const float* cb = (const float*)d_in[4];
    const float* w2 = (const float*)d_in[5];
    const float* b2 = (const float*)d_in[6];
    float* out = (float*)d_out;

    cudaFuncSetAttribute(fused_adapter_kernel,
                         cudaFuncAttributeMaxDynamicSharedMemorySize, SMEM_BYTES);
    fused_adapter_kernel<<<LP * 2, 256, SMEM_BYTES>>>(x, w1, b1, cw, cb, w2, b2, out);
}

// round 3
// speedup vs baseline: 1.1351x; 1.0514x over previous
#include <cuda_runtime.h>
#include <cstdint>
#include <cstddef>

// Problem constants
#define LP   197
#define BT   128
#define DIM  768
#define CA   192
#define TT   8
#define ROWS 64          // rows per CTA (two CTAs per position l)

// SMEM strides (floats), conflict-free fragment access
#define GP   196   // Gs:  64 x 196
#define AP   36    // As:  64 x 36
#define B1P  200   // Bs1: 32 x 200
#define W2P  72    // Ws2: 192 x 72

#define GS_F   (ROWS * GP)          // 12544
#define AS_F   (ROWS * AP)          // 2304
#define BS_F   (192 * W2P)          // 13824 (>= 32*B1P = 6400)
#define SMEM_FLOATS (GS_F + AS_F + BS_F)
#define SMEM_BYTES  (SMEM_FLOATS * 4)   // 114688 B -> 2 CTAs/SM

__device__ __forceinline__ float tf32r(float v) {
    uint32_t u;
    asm("cvt.rna.tf32.f32 %0, %1;" : "=r"(u) : "f"(v));
    return __uint_as_float(u);
}

__device__ __forceinline__ float4 tf32r4(float4 v) {
    v.x = tf32r(v.x); v.y = tf32r(v.y); v.z = tf32r(v.z); v.w = tf32r(v.w);
    return v;
}

__device__ __forceinline__ void mma_tf32(float c[4], const uint32_t a[4], const uint32_t b[2]) {
    asm volatile(
        "mma.sync.aligned.m16n8k8.row.col.f32.tf32.tf32.f32 "
        "{%0,%1,%2,%3}, {%4,%5,%6,%7}, {%8,%9}, {%0,%1,%2,%3};\n"
        : "+f"(c[0]), "+f"(c[1]), "+f"(c[2]), "+f"(c[3])
        : "r"(a[0]), "r"(a[1]), "r"(a[2]), "r"(a[3]),
          "r"(b[0]), "r"(b[1]));
}

__device__ __forceinline__ float gelu_exact(float v) {
    return 0.5f * v * (1.0f + erff(v * 0.70710678118654752f));
}

__global__ void __launch_bounds__(256, 2)
fused_adapter_kernel(const float* __restrict__ x,
                     const float* __restrict__ w1,
                     const float* __restrict__ b1,
                     const float* __restrict__ cw,   // (CA,3)
                     const float* __restrict__ cb,   // (CA,)
                     const float* __restrict__ w2,
                     const float* __restrict__ b2,
                     float* __restrict__ out)
{
    extern __shared__ float smem[];
    float* Gs = smem;                 // 64 x GP
    float* As = smem + GS_F;          // 64 x AP
    float* Bs = As + AS_F;            // union: GEMM1 B chunk / GEMM2 W2 chunk

    const int tid  = threadIdx.x;
    const int wid  = tid >> 5;
    const int lane = tid & 31;
    const int gid  = lane >> 2;   // 0..7
    const int ctig = lane & 3;    // 0..3

    const int l    = blockIdx.x >> 1;
    const int half = blockIdx.x & 1;
    const int lsrc = (l == 0) ? 1 : l;

    const int wm  = wid & 1;
    const int wn1 = wid >> 1;

    // Per-thread staging coordinates (compile-time affine in tid)
    // As stage: 2 float4;  w1 stage: 6 float4;  w2 stage: 12 float4
    const float* xA = x + ((size_t)lsrc * BT + half * ROWS) * DIM;

    // ================= GEMM1 with register-prefetch double buffering ===========
    float acc[2][6][4];
    #pragma unroll
    for (int i = 0; i < 2; i++)
        #pragma unroll
        for (int j = 0; j < 6; j++)
            #pragma unroll
            for (int k = 0; k < 4; k++) acc[i][j][k] = 0.0f;

    float4 xreg[2];
    float4 w1reg[6];

    // prefetch chunk 0
    #pragma unroll
    for (int i = 0; i < 2; i++) {
        int idx = tid + (i << 8);
        int row = idx >> 3;
        int c4  = (idx & 7) << 2;
        xreg[i] = *(const float4*)(xA + (size_t)row * DIM + c4);
    }
    #pragma unroll
    for (int i = 0; i < 6; i++) {
        int idx = tid + (i << 8);
        int row = idx / 48;
        int c4  = (idx % 48) << 2;
        w1reg[i] = *(const float4*)(w1 + (size_t)row * CA + c4);
    }

    #pragma unroll 1
    for (int kc = 0; kc < DIM; kc += 32) {
        // commit prefetched chunk to smem
        #pragma unroll
        for (int i = 0; i < 2; i++) {
            int idx = tid + (i << 8);
            int row = idx >> 3;
            int c4  = (idx & 7) << 2;
            *(float4*)(As + row * AP + c4) = tf32r4(xreg[i]);
        }
        #pragma unroll
        for (int i = 0; i < 6; i++) {
            int idx = tid + (i << 8);
            int row = idx / 48;
            int c4  = (idx % 48) << 2;
            *(float4*)(Bs + row * B1P + c4) = tf32r4(w1reg[i]);
        }
        __syncthreads();

        // prefetch next chunk (overlaps with MMA below)
        if (kc + 32 < DIM) {
            #pragma unroll
            for (int i = 0; i < 2; i++) {
                int idx = tid + (i << 8);
                int row = idx >> 3;
                int c4  = (idx & 7) << 2;
                xreg[i] = *(const float4*)(xA + (size_t)row * DIM + kc + 32 + c4);
            }
            #pragma unroll
            for (int i = 0; i < 6; i++) {
                int idx = tid + (i << 8);
                int row = idx / 48;
                int c4  = (idx % 48) << 2;
                w1reg[i] = *(const float4*)(w1 + (size_t)(kc + 32 + row) * CA + c4);
            }
        }

        #pragma unroll
        for (int ks = 0; ks < 4; ks++) {
            int k0 = ks << 3;
            uint32_t a[2][4];
            #pragma unroll
            for (int mt = 0; mt < 2; mt++) {
                int r0 = wm * 32 + mt * 16 + gid;
                a[mt][0] = __float_as_uint(As[r0 * AP + k0 + ctig]);
                a[mt][1] = __float_as_uint(As[(r0 + 8) * AP + k0 + ctig]);
                a[mt][2] = __float_as_uint(As[r0 * AP + k0 + ctig + 4]);
                a[mt][3] = __float_as_uint(As[(r0 + 8) * AP + k0 + ctig + 4]);
            }
            #pragma unroll
            for (int nt = 0; nt < 6; nt++) {
                uint32_t b[2];
                int n0 = wn1 * 48 + nt * 8 + gid;
                b[0] = __float_as_uint(Bs[(k0 + ctig) * B1P + n0]);
                b[1] = __float_as_uint(Bs[(k0 + ctig + 4) * B1P + n0]);
                mma_tf32(acc[0][nt], a[0], b);
                mma_tf32(acc[1][nt], a[1], b);
            }
        }
        __syncthreads();
    }

    // store h + b1 into Gs
    #pragma unroll
    for (int mt = 0; mt < 2; mt++) {
        #pragma unroll
        for (int nt = 0; nt < 6; nt++) {
            int r0 = wm * 32 + mt * 16 + gid;
            int c0 = wn1 * 48 + nt * 8 + 2 * ctig;
            float bb0 = b1[c0], bb1 = b1[c0 + 1];
            Gs[r0 * GP + c0]           = acc[mt][nt][0] + bb0;
            Gs[r0 * GP + c0 + 1]       = acc[mt][nt][1] + bb1;
            Gs[(r0 + 8) * GP + c0]     = acc[mt][nt][2] + bb0;
            Gs[(r0 + 8) * GP + c0 + 1] = acc[mt][nt][3] + bb1;
        }
    }

    // prefetch GEMM2 w2 chunk 0 into registers (no smem dependency; hides LDG
    // behind mixing + GELU)
    float4 w2reg[12];
    #pragma unroll
    for (int i = 0; i < 12; i++) {
        int idx = tid + (i << 8);
        int row = idx >> 4;
        int c4  = (idx & 15) << 2;
        w2reg[i] = *(const float4*)(w2 + (size_t)row * DIM + c4);
    }

    __syncthreads();

    // ============ Temporal mixing fused with GELU (l >= 1), else GELU only ======
    if (l > 0) {
        #pragma unroll 1
        for (int i = 0; i < 6; i++) {
            int task = tid + (i << 8);          // 8 b-groups * 192 channels
            int b = task / CA;
            int c = task % CA;
            float cw0 = cw[c * 3 + 0];
            float cw1 = cw[c * 3 + 1];
            float cw2 = cw[c * 3 + 2];
            float cbc = cb[c];
            float hv[TT];
            float S = 0.0f;
            #pragma unroll
            for (int t = 0; t < TT; t++) {
                hv[t] = Gs[(b * TT + t) * GP + c];
                float w = cw1 * (float)t - (float)(TT - 1 - t);
                if (t < TT - 1) w += cw0 * (float)(t + 1);
                if (t >= 1)     w += cw2 * (float)(t - 1);
                S += w * hv[t];
            }
            float r = S * (1.0f / 28.0f) + cbc;
            #pragma unroll
            for (int t = 0; t < TT; t++)
                Gs[(b * TT + t) * GP + c] = tf32r(gelu_exact(hv[t] + r));
        }
    } else {
        #pragma unroll 4
        for (int i = 0; i < 48; i++) {
            int idx = tid + (i << 8);
            int r = idx / CA;
            int c = idx % CA;
            Gs[r * GP + c] = tf32r(gelu_exact(Gs[r * GP + c]));
        }
    }
    __syncthreads();

    // ================= GEMM2 with register-prefetch double buffering ============
    const float* xR   = x   + ((size_t)l * BT + half * ROWS) * DIM;
    float*       outR = out + ((size_t)l * BT + half * ROWS) * DIM;

    const int wn2 = wid >> 1;   // 0..3

    #pragma unroll 1
    for (int nc = 0; nc < 12; nc++) {
        int nbase = nc * 64;

        // commit prefetched w2 chunk to smem
        #pragma unroll
        for (int i = 0; i < 12; i++) {
            int idx = tid + (i << 8);
            int row = idx >> 4;
            int c4  = (idx & 15) << 2;
            *(float4*)(Bs + row * W2P + c4) = tf32r4(w2reg[i]);
        }
        __syncthreads();

        // prefetch next w2 chunk (overlaps MMA)
        if (nc + 1 < 12) {
            #pragma unroll
            for (int i = 0; i < 12; i++) {
                int idx = tid + (i << 8);
                int row = idx >> 4;
                int c4  = (idx & 15) << 2;
                w2reg[i] = *(const float4*)(w2 + (size_t)row * DIM + nbase + 64 + c4);
            }
        }

        // prefetch residual x + b2 for epilogue (overlaps MMA)
        float2 xres[2][2][2];
        float2 bb[2];
        #pragma unroll
        for (int nt = 0; nt < 2; nt++) {
            int c0g = nbase + wn2 * 16 + nt * 8 + 2 * ctig;
            bb[nt] = *(const float2*)(b2 + c0g);
            #pragma unroll
            for (int mt = 0; mt < 2; mt++) {
                int r0 = wm * 32 + mt * 16 + gid;
                size_t o0 = (size_t)r0 * DIM + c0g;
                xres[mt][nt][0] = *(const float2*)(xR + o0);
                xres[mt][nt][1] = *(const float2*)(xR + o0 + (size_t)8 * DIM);
            }
        }

        float acc2[2][2][4];
        #pragma unroll
        for (int i = 0; i < 2; i++)
            #pragma unroll
            for (int j = 0; j < 2; j++)
                #pragma unroll
                for (int k = 0; k < 4; k++) acc2[i][j][k] = 0.0f;

        #pragma unroll
        for (int ks = 0; ks < 24; ks++) {
            int k0 = ks << 3;
            uint32_t a[2][4];
            #pragma unroll
            for (int mt = 0; mt < 2; mt++) {
                int r0 = wm * 32 + mt * 16 + gid;
                a[mt][0] = __float_as_uint(Gs[r0 * GP + k0 + ctig]);
                a[mt][1] = __float_as_uint(Gs[(r0 + 8) * GP + k0 + ctig]);
                a[mt][2] = __float_as_uint(Gs[r0 * GP + k0 + ctig + 4]);
                a[mt][3] = __float_as_uint(Gs[(r0 + 8) * GP + k0 + ctig + 4]);
            }
            #pragma unroll
            for (int nt = 0; nt < 2; nt++) {
                uint32_t b[2];
                int n0 = wn2 * 16 + nt * 8 + gid;
                b[0] = __float_as_uint(Bs[(k0 + ctig) * W2P + n0]);
                b[1] = __float_as_uint(Bs[(k0 + ctig + 4) * W2P + n0]);
                mma_tf32(acc2[0][nt], a[0], b);
                mma_tf32(acc2[1][nt], a[1], b);
            }
        }
        __syncthreads();

        // epilogue from registers
        #pragma unroll
        for (int mt = 0; mt < 2; mt++) {
            #pragma unroll
            for (int nt = 0; nt < 2; nt++) {
                int r0  = wm * 32 + mt * 16 + gid;
                int c0g = nbase + wn2 * 16 + nt * 8 + 2 * ctig;
                size_t o0 = (size_t)r0 * DIM + c0g;
                float2 ov0;
                ov0.x = xres[mt][nt][0].x + acc2[mt][nt][0] + bb[nt].x;
                ov0.y = xres[mt][nt][0].y + acc2[mt][nt][1] + bb[nt].y;
                *(float2*)(outR + o0) = ov0;
                float2 ov1;
                ov1.x = xres[mt][nt][1].x + acc2[mt][nt][2] + bb[nt].x;
                ov1.y = xres[mt][nt][1].y + acc2[mt][nt][3] + bb[nt].y;
                *(float2*)(outR + o0 + (size_t)8 * DIM) = ov1;
            }
        }
    }
}

extern "C" void kernel_launch(void* const* d_in, const int* in_sizes, int n_in,
                              void* d_out, int out_size) {
    const float* x  = (const float*)d_in[0];
    const float* w1 = (const float*)d_in[1];
    const float* b1 = (const float*)d_in[2];
    const float* cw = (const float*)d_in[3];
    const float* cb = (const float*)d_in[4];
    const float* w2 = (const float*)d_in[5];
    const float* b2 = (const float*)d_in[6];
    float* out = (float*)d_out;

    cudaFuncSetAttribute(fused_adapter_kernel,
                         cudaFuncAttributeMaxDynamicSharedMemorySize, SMEM_BYTES);
    fused_adapter_kernel<<<LP * 2, 256, SMEM_BYTES>>>(x, w1, b1, cw, cb, w2, b2, out);
}

// round 4
// speedup vs baseline: 1.4732x; 1.2978x over previous
#include <cuda_runtime.h>
#include <cstdint>
#include <cstddef>

// Problem constants
#define LP   197
#define BT   128
#define DIM  768
#define CA   192
#define TT   8
#define ROWS 64          // rows per CTA (two CTAs per position l)

// SMEM strides (floats)
#define GP   196   // Gs: 64 x 196 (h/gelu tile), LDSM-friendly (49 granules/row)
#define AP   36    // A stage: 64 x 36
#define B1P  200   // w1 stage: 32 x 200
#define W2P  72    // w2 stage: 192 x 72

#define GS_F      (ROWS * GP)        // 12544
#define STAGE_A_F (ROWS * AP)        // 2304
#define STAGE_B_F (32 * B1P)         // 6400
#define STAGE_F   (STAGE_A_F + STAGE_B_F)  // 8704  (fits in both GS_F and W_F)
#define W_F       (CA * W2P)         // 13824
#define SMEM_FLOATS (GS_F + W_F)     // 26368
#define SMEM_BYTES  (SMEM_FLOATS * 4)  // 105472 -> 2 CTAs/SM

__device__ __forceinline__ void cp16(uint32_t saddr, const void* gptr) {
    asm volatile("cp.async.cg.shared.global [%0], [%1], 16;\n"
                 :: "r"(saddr), "l"(gptr));
}
__device__ __forceinline__ void cp_commit() { asm volatile("cp.async.commit_group;\n"); }
__device__ __forceinline__ void cp_wait0()  { asm volatile("cp.async.wait_group 0;\n"); }

__device__ __forceinline__ void ldsm_x4(uint32_t a[4], uint32_t saddr) {
    asm volatile("ldmatrix.sync.aligned.m8n8.x4.shared.b16 {%0,%1,%2,%3}, [%4];\n"
                 : "=r"(a[0]), "=r"(a[1]), "=r"(a[2]), "=r"(a[3]) : "r"(saddr));
}

__device__ __forceinline__ void mma_tf32(float c[4], const uint32_t a[4], const uint32_t b[2]) {
    asm volatile(
        "mma.sync.aligned.m16n8k8.row.col.f32.tf32.tf32.f32 "
        "{%0,%1,%2,%3}, {%4,%5,%6,%7}, {%8,%9}, {%0,%1,%2,%3};\n"
        : "+f"(c[0]), "+f"(c[1]), "+f"(c[2]), "+f"(c[3])
        : "r"(a[0]), "r"(a[1]), "r"(a[2]), "r"(a[3]),
          "r"(b[0]), "r"(b[1]));
}

__device__ __forceinline__ float gelu_exact(float v) {
    return 0.5f * v * (1.0f + erff(v * 0.70710678118654752f));
}

__global__ void __launch_bounds__(256, 2)
fused_adapter_kernel(const float* __restrict__ x,
                     const float* __restrict__ w1,
                     const float* __restrict__ b1,
                     const float* __restrict__ cw,   // (CA,3)
                     const float* __restrict__ cb,   // (CA,)
                     const float* __restrict__ w2,
                     const float* __restrict__ b2,
                     float* __restrict__ out)
{
    extern __shared__ float smem[];
    float* Gs = smem;                 // 64 x GP (also GEMM1 odd-chunk stage buffer)
    float* Wr = smem + GS_F;          // w2 stage region (also GEMM1 even-chunk stage)

    const uint32_t smem_u = (uint32_t)__cvta_generic_to_shared(smem);

    const int tid  = threadIdx.x;
    const int wid  = tid >> 5;
    const int lane = tid & 31;
    const int gid  = lane >> 2;   // 0..7
    const int ctig = lane & 3;    // 0..3

    const int l    = blockIdx.x >> 1;
    const int half = blockIdx.x & 1;
    const int lsrc = (l == 0) ? 1 : l;

    const int wm  = wid & 1;
    const int wn1 = wid >> 1;

    // ldmatrix per-lane offsets (words): rows = lane&15, k-half = (lane>>4)*4
    const int a_lane_off = (lane & 15) * AP + ((lane >> 4) << 2);
    const int g_lane_off = (lane & 15) * GP + ((lane >> 4) << 2);

    const float* xA = x + ((size_t)lsrc * BT + half * ROWS) * DIM;

    // ================= GEMM1: ping-pong cp.async, 1 sync/chunk =================
    // buf(i) word base: odd -> 0 (Gs region), even -> GS_F (Wr region)
    float acc[2][6][4];
    #pragma unroll
    for (int i = 0; i < 2; i++)
        #pragma unroll
        for (int j = 0; j < 6; j++)
            #pragma unroll
            for (int k = 0; k < 4; k++) acc[i][j][k] = 0.0f;

    // prologue: stage chunk 0 into even buffer (Wr)
    {
        const uint32_t base_b = smem_u + GS_F * 4;
        #pragma unroll
        for (int i = 0; i < 2; i++) {
            int idx = tid + (i << 8);
            int row = idx >> 3;
            int c4  = (idx & 7) << 2;
            cp16(base_b + (row * AP + c4) * 4, xA + (size_t)row * DIM + c4);
        }
        #pragma unroll
        for (int i = 0; i < 6; i++) {
            int idx = tid + (i << 8);
            int row = idx / 48;
            int c4  = (idx % 48) << 2;
            cp16(base_b + (STAGE_A_F + row * B1P + c4) * 4,
                 w1 + (size_t)row * CA + c4);
        }
        cp_commit();
        cp_wait0();
    }
    __syncthreads();

    #pragma unroll 1
    for (int ic = 0; ic < 24; ic++) {
        const int cur_base  = (ic & 1) ? 0 : GS_F;
        // stage next chunk into the other buffer (async, overlaps MMA)
        if (ic < 23) {
            const int kc = (ic + 1) << 5;
            const uint32_t nb = smem_u + (((ic + 1) & 1) ? 0 : GS_F) * 4;
            #pragma unroll
            for (int i = 0; i < 2; i++) {
                int idx = tid + (i << 8);
                int row = idx >> 3;
                int c4  = (idx & 7) << 2;
                cp16(nb + (row * AP + c4) * 4, xA + (size_t)row * DIM + kc + c4);
            }
            #pragma unroll
            for (int i = 0; i < 6; i++) {
                int idx = tid + (i << 8);
                int row = idx / 48;
                int c4  = (idx % 48) << 2;
                cp16(nb + (STAGE_A_F + row * B1P + c4) * 4,
                     w1 + (size_t)(kc + row) * CA + c4);
            }
            cp_commit();
        }

        const uint32_t As_u = smem_u + cur_base * 4;
        const float*   B1_  = smem + cur_base + STAGE_A_F;

        #pragma unroll
        for (int ks = 0; ks < 4; ks++) {
            int k0 = ks << 3;
            uint32_t a0[4], a1[4];
            ldsm_x4(a0, As_u + ((wm * 32 +  0) * AP + k0 + a_lane_off) * 4);
            ldsm_x4(a1, As_u + ((wm * 32 + 16) * AP + k0 + a_lane_off) * 4);
            #pragma unroll
            for (int nt = 0; nt < 6; nt++) {
                uint32_t b[2];
                int n0 = wn1 * 48 + nt * 8 + gid;
                b[0] = __float_as_uint(B1_[(k0 + ctig) * B1P + n0]);
                b[1] = __float_as_uint(B1_[(k0 + ctig + 4) * B1P + n0]);
                mma_tf32(acc[0][nt], a0, b);
                mma_tf32(acc[1][nt], a1, b);
            }
        }
        if (ic < 23) cp_wait0();
        __syncthreads();
    }

    // store h + b1 into Gs
    #pragma unroll
    for (int mt = 0; mt < 2; mt++) {
        #pragma unroll
        for (int nt = 0; nt < 6; nt++) {
            int r0 = wm * 32 + mt * 16 + gid;
            int c0 = wn1 * 48 + nt * 8 + 2 * ctig;
            float bb0 = b1[c0], bb1 = b1[c0 + 1];
            Gs[r0 * GP + c0]           = acc[mt][nt][0] + bb0;
            Gs[r0 * GP + c0 + 1]       = acc[mt][nt][1] + bb1;
            Gs[(r0 + 8) * GP + c0]     = acc[mt][nt][2] + bb0;
            Gs[(r0 + 8) * GP + c0 + 1] = acc[mt][nt][3] + bb1;
        }
    }

    // prefetch GEMM2 w2 chunk 0 into registers (hidden behind mixing + GELU)
    float4 w2reg[12];
    #pragma unroll
    for (int i = 0; i < 12; i++) {
        int idx = tid + (i << 8);
        int row = idx >> 4;
        int c4  = (idx & 15) << 2;
        w2reg[i] = *(const float4*)(w2 + (size_t)row * DIM + c4);
    }

    __syncthreads();

    // ============ Temporal mixing fused with GELU (l >= 1), else GELU only ======
    if (l > 0) {
        #pragma unroll 1
        for (int i = 0; i < 6; i++) {
            int task = tid + (i << 8);
            int b = task / CA;
            int c = task % CA;
            float cw0 = cw[c * 3 + 0];
            float cw1 = cw[c * 3 + 1];
            float cw2 = cw[c * 3 + 2];
            float cbc = cb[c];
            float hv[TT];
            float S = 0.0f;
            #pragma unroll
            for (int t = 0; t < TT; t++) {
                hv[t] = Gs[(b * TT + t) * GP + c];
                float w = cw1 * (float)t - (float)(TT - 1 - t);
                if (t < TT - 1) w += cw0 * (float)(t + 1);
                if (t >= 1)     w += cw2 * (float)(t - 1);
                S += w * hv[t];
            }
            float r = S * (1.0f / 28.0f) + cbc;
            #pragma unroll
            for (int t = 0; t < TT; t++)
                Gs[(b * TT + t) * GP + c] = gelu_exact(hv[t] + r);
        }
    } else {
        #pragma unroll 4
        for (int i = 0; i < 48; i++) {
            int idx = tid + (i << 8);
            int r = idx / CA;
            int c = idx % CA;
            Gs[r * GP + c] = gelu_exact(Gs[r * GP + c]);
        }
    }
    __syncthreads();

    // ================= GEMM2: register-prefetch double buffering ================
    const float* xR   = x   + ((size_t)l * BT + half * ROWS) * DIM;
    float*       outR = out + ((size_t)l * BT + half * ROWS) * DIM;

    const int wn2 = wid >> 1;   // 0..3
    const uint32_t Gs_u = smem_u;

    #pragma unroll 1
    for (int nc = 0; nc < 12; nc++) {
        int nbase = nc * 64;

        // commit prefetched w2 chunk to smem
        #pragma unroll
        for (int i = 0; i < 12; i++) {
            int idx = tid + (i << 8);
            int row = idx >> 4;
            int c4  = (idx & 15) << 2;
            *(float4*)(Wr + row * W2P + c4) = w2reg[i];
        }
        __syncthreads();

        // prefetch next w2 chunk (overlaps MMA)
        if (nc + 1 < 12) {
            #pragma unroll
            for (int i = 0; i < 12; i++) {
                int idx = tid + (i << 8);
                int row = idx >> 4;
                int c4  = (idx & 15) << 2;
                w2reg[i] = *(const float4*)(w2 + (size_t)row * DIM + nbase + 64 + c4);
            }
        }

        // prefetch residual x + b2 for epilogue (overlaps MMA)
        float2 xres[2][2][2];
        float2 bb[2];
        #pragma unroll
        for (int nt = 0; nt < 2; nt++) {
            int c0g = nbase + wn2 * 16 + nt * 8 + 2 * ctig;
            bb[nt] = *(const float2*)(b2 + c0g);
            #pragma unroll
            for (int mt = 0; mt < 2; mt++) {
                int r0 = wm * 32 + mt * 16 + gid;
                size_t o0 = (size_t)r0 * DIM + c0g;
                xres[mt][nt][0] = *(const float2*)(xR + o0);
                xres[mt][nt][1] = *(const float2*)(xR + o0 + (size_t)8 * DIM);
            }
        }

        float acc2[2][2][4];
        #pragma unroll
        for (int i = 0; i < 2; i++)
            #pragma unroll
            for (int j = 0; j < 2; j++)
                #pragma unroll
                for (int k = 0; k < 4; k++) acc2[i][j][k] = 0.0f;

        #pragma unroll
        for (int ks = 0; ks < 24; ks++) {
            int k0 = ks << 3;
            uint32_t a0[4], a1[4];
            ldsm_x4(a0, Gs_u + ((wm * 32 +  0) * GP + k0 + g_lane_off) * 4);
            ldsm_x4(a1, Gs_u + ((wm * 32 + 16) * GP + k0 + g_lane_off) * 4);
            #pragma unroll
            for (int nt = 0; nt < 2; nt++) {
                uint32_t b[2];
                int n0 = wn2 * 16 + nt * 8 + gid;
                b[0] = __float_as_uint(Wr[(k0 + ctig) * W2P + n0]);
                b[1] = __float_as_uint(Wr[(k0 + ctig + 4) * W2P + n0]);
                mma_tf32(acc2[0][nt], a0, b);
                mma_tf32(acc2[1][nt], a1, b);
            }
        }
        __syncthreads();

        // epilogue from registers
        #pragma unroll
        for (int mt = 0; mt < 2; mt++) {
            #pragma unroll
            for (int nt = 0; nt < 2; nt++) {
                int r0  = wm * 32 + mt * 16 + gid;
                int c0g = nbase + wn2 * 16 + nt * 8 + 2 * ctig;
                size_t o0 = (size_t)r0 * DIM + c0g;
                float2 ov0;
                ov0.x = xres[mt][nt][0].x + acc2[mt][nt][0] + bb[nt].x;
                ov0.y = xres[mt][nt][0].y + acc2[mt][nt][1] + bb[nt].y;
                *(float2*)(outR + o0) = ov0;
                float2 ov1;
                ov1.x = xres[mt][nt][1].x + acc2[mt][nt][2] + bb[nt].x;
                ov1.y = xres[mt][nt][1].y + acc2[mt][nt][3] + bb[nt].y;
                *(float2*)(outR + o0 + (size_t)8 * DIM) = ov1;
            }
        }
    }
}

extern "C" void kernel_launch(void* const* d_in, const int* in_sizes, int n_in,
                              void* d_out, int out_size) {
    const float* x  = (const float*)d_in[0];
    const float* w1 = (const float*)d_in[1];
    const float* b1 = (const float*)d_in[2];
    const float* cw = (const float*)d_in[3];
    const float* cb = (const float*)d_in[4];
    const float* w2 = (const float*)d_in[5];
    const float* b2 = (const float*)d_in[6];
    float* out = (float*)d_out;

    cudaFuncSetAttribute(fused_adapter_kernel,
                         cudaFuncAttributeMaxDynamicSharedMemorySize, SMEM_BYTES);
    fused_adapter_kernel<<<LP * 2, 256, SMEM_BYTES>>>(x, w1, b1, cw, cb, w2, b2, out);
}